// round 16
// baseline (speedup 1.0000x reference)
#include <cuda_runtime.h>
#include <math.h>

#define NROWS   12800     // B*C
#define BATCH   256
#define CDIM    50
#define INPUT   128
#define INTER   64
#define HIDDEN  128
#define NSLOT   11
#define USTRIDE (NSLOT * INTER)      // 704
#define NCHUNK  32
#define RPC     (NROWS / NCHUNK)     // 400 rows per chunk = batches [8bx, 8bx+8)
#define NROUND  13                   // 11 dw slots + 2 hw halves
#define BPG     8                    // batches per chunk / stage2 CTA-group
#define NB      (NCHUNK * NROUND)    // 416 CTAs (<= 148 SMs x 3 -> co-resident)

// Dynamic smem layout (bytes):
//   phase 1:  [0,32768) tws (k-pair interleaved)  [32768,49152) xs
//             [49152,50752) list[400]   [50752,50756) cnt
//   phase 2:  [0,32768) ws (k-pair interleaved)   [32768,34816) as
#define SM_TWS   0
#define SM_XS    32768
#define SM_LIST  49152
#define SM_CNT   50752
#define SM_WS    0
#define SM_AS    32768
#define SMEM_TOTAL 50768

__device__ float g_u[BATCH * USTRIDE];   // zero-init; phase2 rezeroes after read
__device__ float g_acc[BATCH * HIDDEN];  // zero-init; finisher rezeroes
__device__ unsigned g_done[NCHUNK];      // per-chunk barrier tickets (monotonic)
__device__ unsigned g_fin[NCHUNK];       // finisher counters (monotonic)

// Packed fp32x2 FMA: d = a*b + d elementwise on 2 packed floats.
// ptxas never emits FFMA2 from C++; PTX fma.rn.f32x2 is the only route.
__device__ __forceinline__ void ffma2(unsigned long long& d,
                                      unsigned long long a,
                                      unsigned long long b) {
    asm("fma.rn.f32x2 %0, %1, %2, %0;" : "+l"(d) : "l"(a), "l"(b));
}
__device__ __forceinline__ float hsum2(unsigned long long v) {
    float lo, hi;
    asm("mov.b64 {%0, %1}, %2;" : "=f"(lo), "=f"(hi) : "l"(v));
    return lo + hi;
}

__global__ __launch_bounds__(256, 3) void fused_kernel(
    const float* __restrict__ x,     // (B,C,INPUT)
    const int* __restrict__ tc,      // (B,C)
    const int* __restrict__ dc,      // (B,C)
    const int* __restrict__ mask,    // (B,C) bool->int32
    const float* __restrict__ h,     // (B,HIDDEN)
    const float* __restrict__ tw,    // (NSLOT,INPUT,INTER)
    const float* __restrict__ dw,    // (NSLOT,INTER,HIDDEN)
    const float* __restrict__ hw,    // (HIDDEN,HIDDEN)
    float* __restrict__ out)         // (B,HIDDEN)
{
    extern __shared__ __align__(16) char smem[];
    float* tws  = (float*)(smem + SM_TWS);
    int*   list = (int*)(smem + SM_LIST);
    int*   cntp = (int*)(smem + SM_CNT);
    float* ws   = (float*)(smem + SM_WS);
    float* as   = (float*)(smem + SM_AS);
    __shared__ int flag;
    __shared__ unsigned ticket;

    const int id  = blockIdx.x;            // 0..415
    const int t   = threadIdx.x;
    const int bx  = id & 31;               // chunk / phase2 batch group
    const int r   = id >> 5;               // phase2 k-round; == slot s in phase1
    const int bbase = bx * BPG;

    // ======================= PHASE 1: x @ tw[s] ===========================
    if (r < NSLOT) {
        const int s  = r;
        const int r0 = bx * RPC;

        if (t == 0) *cntp = 0;

        // Issue tw[s] loads FIRST (latency overlaps scan). Loaded as k/k+1
        // float2 pairs so the commit can write the k-pair-interleaved layout:
        //   tws2[p][j][e] = tw[2p+e][j]   (p = k/2, e = k&1)
        float2 twA[8], twB[8];
        {
            const float* src = tw + (size_t)s * INPUT * INTER;
            #pragma unroll
            for (int u = 0; u < 8; u++) {
                int q  = t + u * 256;      // 0..2047
                int jp = q & 31;           // j-pair (j = 2jp)
                int p  = q >> 5;           // k-pair 0..63
                twA[u] = *(const float2*)(src + (2 * p)     * INTER + 2 * jp);
                twB[u] = *(const float2*)(src + (2 * p + 1) * INTER + 2 * jp);
            }
        }
        __syncthreads();   // cnt=0 visible before scan's atomicAdd

        for (int i = t; i < RPC; i += 256) {
            int rr = r0 + i;
            if (tc[rr] == s && mask[rr] != 0) {
                int pos = atomicAdd(cntp, 1);
                list[pos] = (dc[rr] << 16) | rr;
            }
        }
        {   // commit interleaved: {w[2p][2jp], w[2p+1][2jp], w[2p][2jp+1], w[2p+1][2jp+1]}
            #pragma unroll
            for (int u = 0; u < 8; u++) {
                int q  = t + u * 256;
                int jp = q & 31;
                int p  = q >> 5;
                *(float4*)(tws + p * 128 + 4 * jp) =
                    make_float4(twA[u].x, twB[u].x, twA[u].y, twB[u].y);
            }
        }
        __syncthreads();   // list + tws ready

        const int n    = *cntp;
        const int warp = t >> 5;
        const int lane = t & 31;
        const int j0   = lane * 2;
        float* xsw = (float*)(smem + SM_XS) + warp * 4 * INPUT;

        // 4-row groups; packed f32x2 accumulation over (even k, odd k).
        for (int i = warp * 4; i < n; i += 32) {
            const int m = n - i;
            const int e0 = list[i];
            const int e1 = (m > 1) ? list[i + 1] : e0;
            const int e2 = (m > 2) ? list[i + 2] : e0;
            const int e3 = (m > 3) ? list[i + 3] : e0;
            const int r0i = e0 & 0xFFFF, d0 = e0 >> 16;
            const int r1i = e1 & 0xFFFF, d1 = e1 >> 16;
            const int r2i = e2 & 0xFFFF, d2 = e2 >> 16;
            const int r3i = e3 & 0xFFFF, d3 = e3 >> 16;

            __syncwarp();
            {
                const float4* x4 = (const float4*)x;
                float4 v0 = x4[(size_t)r0i * 32 + lane];
                float4 v1 = x4[(size_t)r1i * 32 + lane];
                float4 v2 = x4[(size_t)r2i * 32 + lane];
                float4 v3 = x4[(size_t)r3i * 32 + lane];
                *(float4*)(xsw + 0 * INPUT + lane * 4) = v0;
                *(float4*)(xsw + 1 * INPUT + lane * 4) = v1;
                *(float4*)(xsw + 2 * INPUT + lane * 4) = v2;
                *(float4*)(xsw + 3 * INPUT + lane * 4) = v3;
            }
            __syncwarp();

            unsigned long long a0l = 0, a0h = 0, a1l = 0, a1h = 0;
            unsigned long long a2l = 0, a2h = 0, a3l = 0, a3h = 0;
            #pragma unroll 4
            for (int p = 0; p < 64; p++) {
                // One LDS.128: weight pairs for outputs j0 and j0+1 over (2p, 2p+1)
                ulonglong2 w2 = *(const ulonglong2*)(tws + p * 128 + lane * 4);
                unsigned long long v0 = *(const unsigned long long*)(xsw + 0 * INPUT + 2 * p);
                unsigned long long v1 = *(const unsigned long long*)(xsw + 1 * INPUT + 2 * p);
                unsigned long long v2 = *(const unsigned long long*)(xsw + 2 * INPUT + 2 * p);
                unsigned long long v3 = *(const unsigned long long*)(xsw + 3 * INPUT + 2 * p);
                ffma2(a0l, v0, w2.x);  ffma2(a0h, v0, w2.y);
                ffma2(a1l, v1, w2.x);  ffma2(a1h, v1, w2.y);
                ffma2(a2l, v2, w2.x);  ffma2(a2h, v2, w2.y);
                ffma2(a3l, v3, w2.x);  ffma2(a3h, v3, w2.y);
            }

            float* u0 = g_u + (size_t)(r0i / CDIM) * USTRIDE + d0 * INTER + j0;
            atomicAdd(u0,     hsum2(a0l));
            atomicAdd(u0 + 1, hsum2(a0h));
            if (m > 1) {
                float* u1 = g_u + (size_t)(r1i / CDIM) * USTRIDE + d1 * INTER + j0;
                atomicAdd(u1,     hsum2(a1l));
                atomicAdd(u1 + 1, hsum2(a1h));
            }
            if (m > 2) {
                float* u2 = g_u + (size_t)(r2i / CDIM) * USTRIDE + d2 * INTER + j0;
                atomicAdd(u2,     hsum2(a2l));
                atomicAdd(u2 + 1, hsum2(a2h));
            }
            if (m > 3) {
                float* u3 = g_u + (size_t)(r3i / CDIM) * USTRIDE + d3 * INTER + j0;
                atomicAdd(u3,     hsum2(a3l));
                atomicAdd(u3 + 1, hsum2(a3h));
            }
        }
    }
    __syncthreads();   // all warps' atomics issued; p1 smem readers done

    // ====== PER-CHUNK BARRIER, part 1: ARRIVE (before prefetch) ===========
    if (t == 0) {
        __threadfence();
        ticket = atomicAdd(&g_done[bx], 1u);
    }

    // ===== Prefetch of phase-2 W, interleaved over k-pairs ================
    //   ws2[p][hid][e] = W[2p+e][hid]  (p = j/2, e = j&1)
    {
        const float* wsrc = (r < NSLOT)
            ? dw + (size_t)r * 64 * HIDDEN
            : hw + (size_t)(r - NSLOT) * 64 * HIDDEN;
        #pragma unroll
        for (int u = 0; u < 8; u++) {
            int q  = t + u * 256;      // 0..2047
            int hp = q & 63;           // hid-pair (hid = 2hp)
            int p  = q >> 6;           // j-pair 0..31
            float2 A = *(const float2*)(wsrc + (2 * p)     * HIDDEN + 2 * hp);
            float2 B = *(const float2*)(wsrc + (2 * p + 1) * HIDDEN + 2 * hp);
            *(float4*)(ws + p * 256 + 4 * hp) = make_float4(A.x, B.x, A.y, B.y);
        }
    }
    if (r >= NSLOT) {
        #pragma unroll
        for (int i = 0; i < 2; i++) {
            int idx = t + i * 256;
            int bb = idx >> 6, j = idx & 63;
            as[idx] = h[(size_t)(bbase + bb) * HIDDEN + (r - NSLOT) * 64 + j];
        }
    }

    // ====== PER-CHUNK BARRIER, part 2: WAIT ===============================
    __syncthreads();
    if (t == 0) {
        unsigned target = (ticket / (unsigned)NROUND + 1u) * (unsigned)NROUND;
        while (*(volatile unsigned*)&g_done[bx] < target) __nanosleep(32);
        __threadfence();
    }
    __syncthreads();

    // ======================= PHASE 2: flat K-split GEMM (packed) ==========
    if (r < NSLOT) {
        #pragma unroll
        for (int i = 0; i < 2; i++) {
            int idx = t + i * 256;
            int bb = idx >> 6, j = idx & 63;
            float* up = g_u + (size_t)(bbase + bb) * USTRIDE + r * 64 + j;
            float v = *up;
            *up = 0.f;
            as[idx] = v;
        }
        __syncthreads();
    }

    const int bg  = t >> 7;
    const int hid = t & 127;

    unsigned long long c0 = 0, c1 = 0, c2 = 0, c3 = 0;
    #pragma unroll 4
    for (int p = 0; p < 32; p++) {
        unsigned long long w  = *(const unsigned long long*)(ws + p * 256 + hid * 2);
        unsigned long long a0 = *(const unsigned long long*)(as + (bg + 0) * 64 + 2 * p);
        unsigned long long a1 = *(const unsigned long long*)(as + (bg + 2) * 64 + 2 * p);
        unsigned long long a2 = *(const unsigned long long*)(as + (bg + 4) * 64 + 2 * p);
        unsigned long long a3 = *(const unsigned long long*)(as + (bg + 6) * 64 + 2 * p);
        ffma2(c0, a0, w);
        ffma2(c1, a1, w);
        ffma2(c2, a2, w);
        ffma2(c3, a3, w);
    }

    atomicAdd(g_acc + (size_t)(bbase + bg + 0) * HIDDEN + hid, hsum2(c0));
    atomicAdd(g_acc + (size_t)(bbase + bg + 2) * HIDDEN + hid, hsum2(c1));
    atomicAdd(g_acc + (size_t)(bbase + bg + 4) * HIDDEN + hid, hsum2(c2));
    atomicAdd(g_acc + (size_t)(bbase + bg + 6) * HIDDEN + hid, hsum2(c3));

    __threadfence();
    __syncthreads();
    if (t == 0) {
        unsigned c = atomicAdd(&g_fin[bx], 1u);
        flag = ((c % (unsigned)NROUND) == (unsigned)(NROUND - 1)) ? 1 : 0;
    }
    __syncthreads();

    if (flag) {
        #pragma unroll
        for (int i = 0; i < 4; i++) {
            float* p = g_acc + (size_t)(bbase + bg + 2 * i) * HIDDEN + hid;
            float v = __ldcg(p);
            out[(size_t)(bbase + bg + 2 * i) * HIDDEN + hid] =
                1.f / (1.f + expf(-v));
            *p = 0.f;
        }
    }
}

// ---------------------------------------------------------------------------
// kernel_launch: ONE launch, dynamic smem >48KB via attribute opt-in.
// ---------------------------------------------------------------------------
extern "C" void kernel_launch(void* const* d_in, const int* in_sizes, int n_in,
                              void* d_out, int out_size) {
    const float* x    = (const float*)d_in[0];
    const int*   tc   = (const int*)d_in[1];
    const int*   dc   = (const int*)d_in[2];
    const int*   mask = (const int*)d_in[3];
    const float* h    = (const float*)d_in[4];
    const float* tw   = (const float*)d_in[5];
    const float* dw   = (const float*)d_in[6];
    const float* hw   = (const float*)d_in[7];
    float*       out  = (float*)d_out;

    cudaFuncSetAttribute(fused_kernel,
                         cudaFuncAttributeMaxDynamicSharedMemorySize,
                         SMEM_TOTAL);
    fused_kernel<<<NB, 256, SMEM_TOTAL>>>(x, tc, dc, mask, h, tw, dw, hw, out);
}

// round 17
// speedup vs baseline: 1.0057x; 1.0057x over previous
#include <cuda_runtime.h>
#include <math.h>

#define NROWS   12800     // B*C
#define BATCH   256
#define CDIM    50
#define INPUT   128
#define INTER   64
#define HIDDEN  128
#define NSLOT   11
#define USTRIDE (NSLOT * INTER)      // 704
#define NCHUNK  32
#define RPC     (NROWS / NCHUNK)     // 400 rows per chunk = batches [8bx, 8bx+8)
#define NROUND  13                   // 11 dw slots + 2 hw halves
#define BPG     8                    // batches per chunk / stage2 CTA-group
#define NB      (NCHUNK * NROUND)    // 416 CTAs

// Dynamic smem layout (bytes):
//   phase 1:  [0,32768) tws (k-pair interleaved)  [32768,49152) xs
//             [49152,50752) list[400]   [50752,50756) cnt
//   phase 2:  [0,32768) ws (k-pair interleaved)   [32768,34816) as
#define SM_TWS   0
#define SM_XS    32768
#define SM_LIST  49152
#define SM_CNT   50752
#define SM_WS    0
#define SM_AS    32768
#define SMEM_TOTAL 50768

__device__ float g_u[BATCH * USTRIDE];   // zero-init; phase2 rezeroes after read
__device__ float g_acc[BATCH * HIDDEN];  // zero-init; finisher rezeroes
__device__ unsigned g_done[NCHUNK];      // per-chunk barrier tickets (monotonic)
__device__ unsigned g_fin[NCHUNK];       // finisher counters (monotonic)

// Packed fp32x2 FMA (Blackwell FFMA2; only reachable via PTX).
__device__ __forceinline__ void ffma2(unsigned long long& d,
                                      unsigned long long a,
                                      unsigned long long b) {
    asm("fma.rn.f32x2 %0, %1, %2, %0;" : "+l"(d) : "l"(a), "l"(b));
}
__device__ __forceinline__ float hsum2(unsigned long long v) {
    float lo, hi;
    asm("mov.b64 {%0, %1}, %2;" : "=f"(lo), "=f"(hi) : "l"(v));
    return lo + hi;
}

// launch_bounds(256, 4): cap regs at 64 so FOUR CTAs fit per SM
// (4 x 50.8KB smem = 203KB < 228KB; 4 x 256 x 64 = 64K regs).
__global__ __launch_bounds__(256, 4) void fused_kernel(
    const float* __restrict__ x,     // (B,C,INPUT)
    const int* __restrict__ tc,      // (B,C)
    const int* __restrict__ dc,      // (B,C)
    const int* __restrict__ mask,    // (B,C) bool->int32
    const float* __restrict__ h,     // (B,HIDDEN)
    const float* __restrict__ tw,    // (NSLOT,INPUT,INTER)
    const float* __restrict__ dw,    // (NSLOT,INTER,HIDDEN)
    const float* __restrict__ hw,    // (HIDDEN,HIDDEN)
    float* __restrict__ out)         // (B,HIDDEN)
{
    extern __shared__ __align__(16) char smem[];
    float* tws  = (float*)(smem + SM_TWS);
    int*   list = (int*)(smem + SM_LIST);
    int*   cntp = (int*)(smem + SM_CNT);
    float* ws   = (float*)(smem + SM_WS);
    float* as   = (float*)(smem + SM_AS);
    __shared__ int flag;
    __shared__ unsigned ticket;

    const int id  = blockIdx.x;            // 0..415
    const int t   = threadIdx.x;
    const int bx  = id & 31;               // chunk / phase2 batch group
    const int r   = id >> 5;               // phase2 k-round; == slot s in phase1
    const int bbase = bx * BPG;

    // ======================= PHASE 1: x @ tw[s] ===========================
    if (r < NSLOT) {
        const int s  = r;
        const int r0 = bx * RPC;

        if (t == 0) *cntp = 0;
        __syncthreads();   // cnt=0 visible before scan's atomicAdd

        // Scan (small) — compiler may interleave with the tw load below.
        for (int i = t; i < RPC; i += 256) {
            int rr = r0 + i;
            if (tc[rr] == s && mask[rr] != 0) {
                int pos = atomicAdd(cntp, 1);
                list[pos] = (dc[rr] << 16) | rr;
            }
        }

        // tw[s] -> smem, k-pair interleaved:
        //   tws2[p][j][e] = tw[2p+e][j]   (p = k/2, e = k&1)
        {
            const float* src = tw + (size_t)s * INPUT * INTER;
            #pragma unroll
            for (int u = 0; u < 8; u++) {
                int q  = t + u * 256;      // 0..2047
                int jp = q & 31;           // j-pair (j = 2jp)
                int p  = q >> 5;           // k-pair 0..63
                float2 A = *(const float2*)(src + (2 * p)     * INTER + 2 * jp);
                float2 B = *(const float2*)(src + (2 * p + 1) * INTER + 2 * jp);
                *(float4*)(tws + p * 128 + 4 * jp) =
                    make_float4(A.x, B.x, A.y, B.y);
            }
        }
        __syncthreads();   // list + tws ready

        const int n    = *cntp;
        const int warp = t >> 5;
        const int lane = t & 31;
        const int j0   = lane * 2;
        float* xsw = (float*)(smem + SM_XS) + warp * 4 * INPUT;

        // 4-row groups; packed f32x2 accumulation over (even k, odd k).
        for (int i = warp * 4; i < n; i += 32) {
            const int m = n - i;
            const int e0 = list[i];
            const int e1 = (m > 1) ? list[i + 1] : e0;
            const int e2 = (m > 2) ? list[i + 2] : e0;
            const int e3 = (m > 3) ? list[i + 3] : e0;
            const int r0i = e0 & 0xFFFF, d0 = e0 >> 16;
            const int r1i = e1 & 0xFFFF, d1 = e1 >> 16;
            const int r2i = e2 & 0xFFFF, d2 = e2 >> 16;
            const int r3i = e3 & 0xFFFF, d3 = e3 >> 16;

            __syncwarp();
            {
                const float4* x4 = (const float4*)x;
                float4 v0 = x4[(size_t)r0i * 32 + lane];
                float4 v1 = x4[(size_t)r1i * 32 + lane];
                float4 v2 = x4[(size_t)r2i * 32 + lane];
                float4 v3 = x4[(size_t)r3i * 32 + lane];
                *(float4*)(xsw + 0 * INPUT + lane * 4) = v0;
                *(float4*)(xsw + 1 * INPUT + lane * 4) = v1;
                *(float4*)(xsw + 2 * INPUT + lane * 4) = v2;
                *(float4*)(xsw + 3 * INPUT + lane * 4) = v3;
            }
            __syncwarp();

            unsigned long long a0l = 0, a0h = 0, a1l = 0, a1h = 0;
            unsigned long long a2l = 0, a2h = 0, a3l = 0, a3h = 0;
            #pragma unroll 4
            for (int p = 0; p < 64; p++) {
                ulonglong2 w2 = *(const ulonglong2*)(tws + p * 128 + lane * 4);
                unsigned long long v0 = *(const unsigned long long*)(xsw + 0 * INPUT + 2 * p);
                unsigned long long v1 = *(const unsigned long long*)(xsw + 1 * INPUT + 2 * p);
                unsigned long long v2 = *(const unsigned long long*)(xsw + 2 * INPUT + 2 * p);
                unsigned long long v3 = *(const unsigned long long*)(xsw + 3 * INPUT + 2 * p);
                ffma2(a0l, v0, w2.x);  ffma2(a0h, v0, w2.y);
                ffma2(a1l, v1, w2.x);  ffma2(a1h, v1, w2.y);
                ffma2(a2l, v2, w2.x);  ffma2(a2h, v2, w2.y);
                ffma2(a3l, v3, w2.x);  ffma2(a3h, v3, w2.y);
            }

            float* u0 = g_u + (size_t)(r0i / CDIM) * USTRIDE + d0 * INTER + j0;
            atomicAdd(u0,     hsum2(a0l));
            atomicAdd(u0 + 1, hsum2(a0h));
            if (m > 1) {
                float* u1 = g_u + (size_t)(r1i / CDIM) * USTRIDE + d1 * INTER + j0;
                atomicAdd(u1,     hsum2(a1l));
                atomicAdd(u1 + 1, hsum2(a1h));
            }
            if (m > 2) {
                float* u2 = g_u + (size_t)(r2i / CDIM) * USTRIDE + d2 * INTER + j0;
                atomicAdd(u2,     hsum2(a2l));
                atomicAdd(u2 + 1, hsum2(a2h));
            }
            if (m > 3) {
                float* u3 = g_u + (size_t)(r3i / CDIM) * USTRIDE + d3 * INTER + j0;
                atomicAdd(u3,     hsum2(a3l));
                atomicAdd(u3 + 1, hsum2(a3h));
            }
        }
    }
    __syncthreads();   // all warps' atomics issued; p1 smem readers done

    // ====== PER-CHUNK BARRIER, part 1: ARRIVE (before prefetch) ===========
    if (t == 0) {
        __threadfence();
        ticket = atomicAdd(&g_done[bx], 1u);
    }

    // ===== Prefetch of phase-2 W, interleaved over k-pairs ================
    {
        const float* wsrc = (r < NSLOT)
            ? dw + (size_t)r * 64 * HIDDEN
            : hw + (size_t)(r - NSLOT) * 64 * HIDDEN;
        #pragma unroll
        for (int u = 0; u < 8; u++) {
            int q  = t + u * 256;      // 0..2047
            int hp = q & 63;           // hid-pair (hid = 2hp)
            int p  = q >> 6;           // j-pair 0..31
            float2 A = *(const float2*)(wsrc + (2 * p)     * HIDDEN + 2 * hp);
            float2 B = *(const float2*)(wsrc + (2 * p + 1) * HIDDEN + 2 * hp);
            *(float4*)(ws + p * 256 + 4 * hp) = make_float4(A.x, B.x, A.y, B.y);
        }
    }
    if (r >= NSLOT) {
        #pragma unroll
        for (int i = 0; i < 2; i++) {
            int idx = t + i * 256;
            int bb = idx >> 6, j = idx & 63;
            as[idx] = h[(size_t)(bbase + bb) * HIDDEN + (r - NSLOT) * 64 + j];
        }
    }

    // ====== PER-CHUNK BARRIER, part 2: WAIT ===============================
    __syncthreads();
    if (t == 0) {
        unsigned target = (ticket / (unsigned)NROUND + 1u) * (unsigned)NROUND;
        while (*(volatile unsigned*)&g_done[bx] < target) __nanosleep(32);
        __threadfence();
    }
    __syncthreads();

    // ======================= PHASE 2: flat K-split GEMM (packed) ==========
    if (r < NSLOT) {
        #pragma unroll
        for (int i = 0; i < 2; i++) {
            int idx = t + i * 256;
            int bb = idx >> 6, j = idx & 63;
            float* up = g_u + (size_t)(bbase + bb) * USTRIDE + r * 64 + j;
            float v = *up;
            *up = 0.f;
            as[idx] = v;
        }
        __syncthreads();
    }

    const int bg  = t >> 7;
    const int hid = t & 127;

    unsigned long long c0 = 0, c1 = 0, c2 = 0, c3 = 0;
    #pragma unroll 4
    for (int p = 0; p < 32; p++) {
        unsigned long long w  = *(const unsigned long long*)(ws + p * 256 + hid * 2);
        unsigned long long a0 = *(const unsigned long long*)(as + (bg + 0) * 64 + 2 * p);
        unsigned long long a1 = *(const unsigned long long*)(as + (bg + 2) * 64 + 2 * p);
        unsigned long long a2 = *(const unsigned long long*)(as + (bg + 4) * 64 + 2 * p);
        unsigned long long a3 = *(const unsigned long long*)(as + (bg + 6) * 64 + 2 * p);
        ffma2(c0, a0, w);
        ffma2(c1, a1, w);
        ffma2(c2, a2, w);
        ffma2(c3, a3, w);
    }

    atomicAdd(g_acc + (size_t)(bbase + bg + 0) * HIDDEN + hid, hsum2(c0));
    atomicAdd(g_acc + (size_t)(bbase + bg + 2) * HIDDEN + hid, hsum2(c1));
    atomicAdd(g_acc + (size_t)(bbase + bg + 4) * HIDDEN + hid, hsum2(c2));
    atomicAdd(g_acc + (size_t)(bbase + bg + 6) * HIDDEN + hid, hsum2(c3));

    __threadfence();
    __syncthreads();
    if (t == 0) {
        unsigned c = atomicAdd(&g_fin[bx], 1u);
        flag = ((c % (unsigned)NROUND) == (unsigned)(NROUND - 1)) ? 1 : 0;
    }
    __syncthreads();

    if (flag) {
        #pragma unroll
        for (int i = 0; i < 4; i++) {
            float* p = g_acc + (size_t)(bbase + bg + 2 * i) * HIDDEN + hid;
            float v = __ldcg(p);
            out[(size_t)(bbase + bg + 2 * i) * HIDDEN + hid] =
                1.f / (1.f + expf(-v));
            *p = 0.f;
        }
    }
}

// ---------------------------------------------------------------------------
// kernel_launch: ONE launch, dynamic smem >48KB via attribute opt-in.
// ---------------------------------------------------------------------------
extern "C" void kernel_launch(void* const* d_in, const int* in_sizes, int n_in,
                              void* d_out, int out_size) {
    const float* x    = (const float*)d_in[0];
    const int*   tc   = (const int*)d_in[1];
    const int*   dc   = (const int*)d_in[2];
    const int*   mask = (const int*)d_in[3];
    const float* h    = (const float*)d_in[4];
    const float* tw   = (const float*)d_in[5];
    const float* dw   = (const float*)d_in[6];
    const float* hw   = (const float*)d_in[7];
    float*       out  = (float*)d_out;

    cudaFuncSetAttribute(fused_kernel,
                         cudaFuncAttributeMaxDynamicSharedMemorySize,
                         SMEM_TOTAL);
    fused_kernel<<<NB, 256, SMEM_TOTAL>>>(x, tc, dc, mask, h, tw, dw, hw, out);
}